// round 1
// baseline (speedup 1.0000x reference)
#include <cuda_runtime.h>
#include <cstdint>

#define BATCH 4
#define S_LEN 4096
#define D_MODEL 1024

// Scratch (module-load allocations, legal per harness rules)
__device__ float g_qkv[(size_t)BATCH * S_LEN * 3 * D_MODEL];     // [B,S,3D] 201MB
__device__ float g_logits[(size_t)BATCH * S_LEN * S_LEN];        // [B,S,S]  268MB
__device__ float g_attn[(size_t)BATCH * S_LEN * D_MODEL];        // [B,S,D]   67MB

#define BM 128
#define BN 128
#define BK 16
#define PS 20   // padded smem stride (BK+4): conflict-free fragment reads

__device__ __forceinline__ uint32_t f2tf(float x) {
    uint32_t u;
    asm("cvt.rna.tf32.f32 %0, %1;" : "=r"(u) : "f"(x));
    return u;
}

__device__ __forceinline__ void mma8(float* c, const uint32_t* a, const uint32_t* b) {
    asm volatile(
        "mma.sync.aligned.m16n8k8.row.col.f32.tf32.tf32.f32 "
        "{%0,%1,%2,%3}, {%4,%5,%6,%7}, {%8,%9}, {%0,%1,%2,%3};\n"
        : "+f"(c[0]), "+f"(c[1]), "+f"(c[2]), "+f"(c[3])
        : "r"(a[0]), "r"(a[1]), "r"(a[2]), "r"(a[3]),
          "r"(b[0]), "r"(b[1]));
}

// C[M,N] = alpha * A[M,K] @ op(B).  BT=true: B is [N,K] row-major (compute A@B^T).
// BT=false: B is [K,N] row-major. Batched via blockIdx.z with element strides.
// All dims assumed multiples of tile sizes (true for all 4 GEMMs here).
template<bool BT>
__global__ __launch_bounds__(256, 2)
void gemm_tf32(const float* __restrict__ A, const float* __restrict__ B,
               float* __restrict__ C, int Kd,
               int lda, int ldb, int ldc,
               size_t sA, size_t sB, size_t sC, float alpha)
{
    __shared__ uint32_t As[2][BM * PS];
    __shared__ uint32_t Bs[2][BN * PS];

    const int tid = threadIdx.x;
    const float* Ab = A + sA * blockIdx.z;
    const float* Bb = B + sB * blockIdx.z;
    float*       Cb = C + sC * blockIdx.z;

    const int cta_m = blockIdx.y * BM;
    const int cta_n = blockIdx.x * BN;

    const int warp = tid >> 5;
    const int lane = tid & 31;
    const int gid  = lane >> 2;   // 0..7
    const int tig  = lane & 3;    // 0..3
    const int wm   = (warp & 3) * 32;   // 4 warps along M
    const int wn   = (warp >> 2) * 64;  // 2 warps along N

    float acc[2][8][4];
    #pragma unroll
    for (int i = 0; i < 2; i++)
        #pragma unroll
        for (int j = 0; j < 8; j++)
            #pragma unroll
            for (int k = 0; k < 4; k++) acc[i][j][k] = 0.f;

    // A tile loader geometry: 128 rows x 16 cols, 2 float4 per thread
    const int a_row = tid >> 2;          // 0..63 (and +64)
    const int a_col = (tid & 3) * 4;     // 0,4,8,12
    const float* Aptr = Ab + (size_t)(cta_m + a_row) * lda + a_col;

    // B tile loader geometry
    const float* Bptr;
    int bn_row = 0, bn_col = 0;
    if (BT) {
        Bptr = Bb + (size_t)(cta_n + a_row) * ldb + a_col;
    } else {
        bn_row = tid >> 5;               // 0..7 (and +8)
        bn_col = (tid & 31) * 4;         // 0..124
        Bptr = Bb + (size_t)bn_row * ldb + cta_n + bn_col;
    }

    const int KT = Kd / BK;

    // ---- prologue: fill stage 0 ----
    {
        float4 a0 = *(const float4*)Aptr;
        float4 a1 = *(const float4*)(Aptr + (size_t)64 * lda);
        uint4 u0 = make_uint4(f2tf(a0.x), f2tf(a0.y), f2tf(a0.z), f2tf(a0.w));
        uint4 u1 = make_uint4(f2tf(a1.x), f2tf(a1.y), f2tf(a1.z), f2tf(a1.w));
        *(uint4*)&As[0][(size_t)a_row * PS + a_col] = u0;
        *(uint4*)&As[0][(size_t)(a_row + 64) * PS + a_col] = u1;
        if (BT) {
            float4 b0 = *(const float4*)Bptr;
            float4 b1 = *(const float4*)(Bptr + (size_t)64 * ldb);
            uint4 v0 = make_uint4(f2tf(b0.x), f2tf(b0.y), f2tf(b0.z), f2tf(b0.w));
            uint4 v1 = make_uint4(f2tf(b1.x), f2tf(b1.y), f2tf(b1.z), f2tf(b1.w));
            *(uint4*)&Bs[0][(size_t)a_row * PS + a_col] = v0;
            *(uint4*)&Bs[0][(size_t)(a_row + 64) * PS + a_col] = v1;
        } else {
            float4 b0 = *(const float4*)Bptr;
            float4 b1 = *(const float4*)(Bptr + (size_t)8 * ldb);
            const float* p0 = &b0.x; const float* p1 = &b1.x;
            #pragma unroll
            for (int i = 0; i < 4; i++) {
                Bs[0][(size_t)(bn_col + i) * PS + bn_row]     = f2tf(p0[i]);
                Bs[0][(size_t)(bn_col + i) * PS + bn_row + 8] = f2tf(p1[i]);
            }
        }
    }
    __syncthreads();

    // ---- mainloop ----
    for (int kt = 0; kt < KT; kt++) {
        const int cur = kt & 1;
        const bool has_next = (kt + 1 < KT);
        float4 la0, la1, lb0, lb1;
        if (has_next) {
            const float* ap = Aptr + (kt + 1) * BK;
            la0 = *(const float4*)ap;
            la1 = *(const float4*)(ap + (size_t)64 * lda);
            if (BT) {
                const float* bp = Bptr + (kt + 1) * BK;
                lb0 = *(const float4*)bp;
                lb1 = *(const float4*)(bp + (size_t)64 * ldb);
            } else {
                const float* bp = Bptr + (size_t)(kt + 1) * BK * ldb;
                lb0 = *(const float4*)bp;
                lb1 = *(const float4*)(bp + (size_t)8 * ldb);
            }
        }

        // compute on stage `cur`
        #pragma unroll
        for (int k0 = 0; k0 < BK; k0 += 8) {
            uint32_t af[2][4], bfr[8][2];
            #pragma unroll
            for (int mt = 0; mt < 2; mt++) {
                int r = wm + mt * 16 + gid;
                af[mt][0] = As[cur][(size_t)r * PS + k0 + tig];
                af[mt][1] = As[cur][(size_t)(r + 8) * PS + k0 + tig];
                af[mt][2] = As[cur][(size_t)r * PS + k0 + tig + 4];
                af[mt][3] = As[cur][(size_t)(r + 8) * PS + k0 + tig + 4];
            }
            #pragma unroll
            for (int nt = 0; nt < 8; nt++) {
                int cc = wn + nt * 8 + gid;
                bfr[nt][0] = Bs[cur][(size_t)cc * PS + k0 + tig];
                bfr[nt][1] = Bs[cur][(size_t)cc * PS + k0 + tig + 4];
            }
            #pragma unroll
            for (int mt = 0; mt < 2; mt++)
                #pragma unroll
                for (int nt = 0; nt < 8; nt++)
                    mma8(acc[mt][nt], af[mt], bfr[nt]);
        }

        if (has_next) {
            const int nb = cur ^ 1;
            uint4 u0 = make_uint4(f2tf(la0.x), f2tf(la0.y), f2tf(la0.z), f2tf(la0.w));
            uint4 u1 = make_uint4(f2tf(la1.x), f2tf(la1.y), f2tf(la1.z), f2tf(la1.w));
            *(uint4*)&As[nb][(size_t)a_row * PS + a_col] = u0;
            *(uint4*)&As[nb][(size_t)(a_row + 64) * PS + a_col] = u1;
            if (BT) {
                uint4 v0 = make_uint4(f2tf(lb0.x), f2tf(lb0.y), f2tf(lb0.z), f2tf(lb0.w));
                uint4 v1 = make_uint4(f2tf(lb1.x), f2tf(lb1.y), f2tf(lb1.z), f2tf(lb1.w));
                *(uint4*)&Bs[nb][(size_t)a_row * PS + a_col] = v0;
                *(uint4*)&Bs[nb][(size_t)(a_row + 64) * PS + a_col] = v1;
            } else {
                const float* p0 = &lb0.x; const float* p1 = &lb1.x;
                #pragma unroll
                for (int i = 0; i < 4; i++) {
                    Bs[nb][(size_t)(bn_col + i) * PS + bn_row]     = f2tf(p0[i]);
                    Bs[nb][(size_t)(bn_col + i) * PS + bn_row + 8] = f2tf(p1[i]);
                }
            }
        }
        __syncthreads();
    }

    // ---- epilogue ----
    #pragma unroll
    for (int mt = 0; mt < 2; mt++) {
        int row0 = cta_m + wm + mt * 16 + gid;
        #pragma unroll
        for (int nt = 0; nt < 8; nt++) {
            int col = cta_n + wn + nt * 8 + tig * 2;
            float2 lo = make_float2(acc[mt][nt][0] * alpha, acc[mt][nt][1] * alpha);
            float2 hi = make_float2(acc[mt][nt][2] * alpha, acc[mt][nt][3] * alpha);
            *(float2*)&Cb[(size_t)row0 * ldc + col] = lo;
            *(float2*)&Cb[(size_t)(row0 + 8) * ldc + col] = hi;
        }
    }
}

// Row softmax over length-4096 rows; one block (256 threads) per row.
__global__ void softmax_rows(float* __restrict__ logits)
{
    __shared__ float red[8];
    __shared__ float bcast;
    const size_t row = blockIdx.x;
    float* p = logits + row * (size_t)S_LEN;
    const int tid = threadIdx.x;
    const int lane = tid & 31, wid = tid >> 5;

    float4 v[4];
    float m = -3.4e38f;
    #pragma unroll
    for (int i = 0; i < 4; i++) {
        v[i] = *(const float4*)(p + tid * 4 + i * 1024);
        m = fmaxf(m, fmaxf(fmaxf(v[i].x, v[i].y), fmaxf(v[i].z, v[i].w)));
    }
    #pragma unroll
    for (int o = 16; o; o >>= 1) m = fmaxf(m, __shfl_xor_sync(0xffffffffu, m, o));
    if (lane == 0) red[wid] = m;
    __syncthreads();
    if (tid == 0) {
        float mm = red[0];
        #pragma unroll
        for (int i = 1; i < 8; i++) mm = fmaxf(mm, red[i]);
        bcast = mm;
    }
    __syncthreads();
    m = bcast;

    float s = 0.f;
    #pragma unroll
    for (int i = 0; i < 4; i++) {
        v[i].x = __expf(v[i].x - m);
        v[i].y = __expf(v[i].y - m);
        v[i].z = __expf(v[i].z - m);
        v[i].w = __expf(v[i].w - m);
        s += v[i].x + v[i].y + v[i].z + v[i].w;
    }
    #pragma unroll
    for (int o = 16; o; o >>= 1) s += __shfl_xor_sync(0xffffffffu, s, o);
    if (lane == 0) red[wid] = s;
    __syncthreads();
    if (tid == 0) {
        float ss = 0.f;
        #pragma unroll
        for (int i = 0; i < 8; i++) ss += red[i];
        bcast = 1.0f / ss;
    }
    __syncthreads();
    const float inv = bcast;

    #pragma unroll
    for (int i = 0; i < 4; i++) {
        v[i].x *= inv; v[i].y *= inv; v[i].z *= inv; v[i].w *= inv;
        *(float4*)(p + tid * 4 + i * 1024) = v[i];
    }
}

extern "C" void kernel_launch(void* const* d_in, const int* in_sizes, int n_in,
                              void* d_out, int out_size)
{
    const float* x    = (const float*)d_in[0];
    const float* wqkv = (const float*)d_in[1];
    const float* wo   = (const float*)d_in[2];
    float* out        = (float*)d_out;

    float *qkv, *logits, *attn;
    cudaGetSymbolAddress((void**)&qkv,    g_qkv);
    cudaGetSymbolAddress((void**)&logits, g_logits);
    cudaGetSymbolAddress((void**)&attn,   g_attn);

    const int BS = BATCH * S_LEN;                 // 16384
    const size_t qkv_bstride = (size_t)S_LEN * 3 * D_MODEL;
    const size_t log_bstride = (size_t)S_LEN * S_LEN;
    const size_t att_bstride = (size_t)S_LEN * D_MODEL;

    // 1) qkv = x @ W_qkv^T            [16384,3072,K=1024]
    gemm_tf32<true><<<dim3(3 * D_MODEL / BN, BS / BM, 1), 256>>>(
        x, wqkv, qkv, D_MODEL,
        D_MODEL, D_MODEL, 3 * D_MODEL,
        0, 0, 0, 1.0f);

    // 2) logits = (Q @ K^T) / 32      [4096,4096,K=1024] x4 batches
    gemm_tf32<true><<<dim3(S_LEN / BN, S_LEN / BM, BATCH), 256>>>(
        qkv, qkv + D_MODEL, logits, D_MODEL,
        3 * D_MODEL, 3 * D_MODEL, S_LEN,
        qkv_bstride, qkv_bstride, log_bstride, 0.03125f);

    // 3) softmax rows
    softmax_rows<<<BS, 256>>>(logits);

    // 4) attn = weights @ V           [4096,1024,K=4096] x4, NN
    gemm_tf32<false><<<dim3(D_MODEL / BN, S_LEN / BM, BATCH), 256>>>(
        logits, qkv + 2 * D_MODEL, attn, S_LEN,
        S_LEN, 3 * D_MODEL, D_MODEL,
        log_bstride, qkv_bstride, att_bstride, 1.0f);

    // 5) out = attn @ W_o^T           [16384,1024,K=1024]
    gemm_tf32<true><<<dim3(D_MODEL / BN, BS / BM, 1), 256>>>(
        attn, wo, out, D_MODEL,
        D_MODEL, D_MODEL, D_MODEL,
        0, 0, 0, 1.0f);
}

// round 3
// speedup vs baseline: 3.3215x; 3.3215x over previous
#include <cuda_runtime.h>
#include <cuda_fp16.h>
#include <cstdint>

#define BATCH 4
#define S_LEN 4096
#define D_MODEL 1024

// ---------------- scratch (module-load device globals) ----------------
__device__ float  g_logits[(size_t)BATCH * S_LEN * S_LEN];              // fp32 [B,S,S]
__device__ __half g_ph[(size_t)BATCH * S_LEN * S_LEN];                  // fp16 softmax(P)
__device__ __half g_qkvh[(size_t)BATCH * S_LEN * 3 * D_MODEL];          // fp16 [B,S,3D]
__device__ __half g_xh[(size_t)BATCH * S_LEN * D_MODEL];                // fp16 x
__device__ __half g_wqkvh[(size_t)3 * D_MODEL * D_MODEL];               // fp16 W_qkv
__device__ __half g_woh[(size_t)D_MODEL * D_MODEL];                     // fp16 W_o
__device__ __half g_vth[(size_t)BATCH * D_MODEL * S_LEN];               // fp16 V^T [B,D,S]
__device__ __half g_attnh[(size_t)BATCH * S_LEN * D_MODEL];             // fp16 attn

// ---------------- helpers ----------------
__device__ __forceinline__ uint32_t smem_u32(const void* p) {
    uint32_t a;
    asm("{ .reg .u64 t; cvta.to.shared.u64 t, %1; cvt.u32.u64 %0, t; }" : "=r"(a) : "l"(p));
    return a;
}
__device__ __forceinline__ void cp16(uint32_t dst, const void* src) {
    asm volatile("cp.async.cg.shared.global [%0], [%1], 16;" :: "r"(dst), "l"(src));
}
__device__ __forceinline__ void ldsm_x4(uint32_t* r, uint32_t addr) {
    asm volatile("ldmatrix.sync.aligned.m8n8.x4.shared.b16 {%0,%1,%2,%3}, [%4];"
                 : "=r"(r[0]), "=r"(r[1]), "=r"(r[2]), "=r"(r[3]) : "r"(addr));
}
__device__ __forceinline__ void mma16816(float* c, const uint32_t* a, const uint32_t* b) {
    asm volatile(
        "mma.sync.aligned.m16n8k16.row.col.f32.f16.f16.f32 "
        "{%0,%1,%2,%3}, {%4,%5,%6,%7}, {%8,%9}, {%0,%1,%2,%3};"
        : "+f"(c[0]), "+f"(c[1]), "+f"(c[2]), "+f"(c[3])
        : "r"(a[0]), "r"(a[1]), "r"(a[2]), "r"(a[3]), "r"(b[0]), "r"(b[1]));
}

// ---------------- fp16 NT GEMM: C[M,N] = alpha * A[M,K] @ B[N,K]^T ----------------
// CTA tile 128x128, BK=64 (128B rows), 3-stage cp.async pipeline, ldmatrix feeds.
#define TM 128
#define TN 128
#define TBK 64
#define A_BYTES (TM * TBK * 2)            // 16384
#define STAGE_BYTES ((TM + TN) * TBK * 2) // 32768
#define NSTAGE 3
#define SMEM_TOTAL (NSTAGE * STAGE_BYTES) // 98304

template<bool OUT_HALF>
__global__ void __launch_bounds__(256, 2)
gemm_f16(const __half* __restrict__ A, const __half* __restrict__ B, void* __restrict__ Cv,
         int Kd, int lda, int ldb, int ldc,
         size_t sA, size_t sB, size_t sC, float alpha)
{
    extern __shared__ char smem[];
    const uint32_t sb = smem_u32(smem);
    const int tid  = threadIdx.x;
    const int warp = tid >> 5, lane = tid & 31;
    const int wm = (warp & 3) * 32;       // 4 warps along M
    const int wn = (warp >> 2) * 64;      // 2 warps along N

    const int cta_m = blockIdx.y * TM;
    const int cta_n = blockIdx.x * TN;
    const __half* Ab = A + sA * blockIdx.z + (size_t)cta_m * lda;
    const __half* Bb = B + sB * blockIdx.z + (size_t)cta_n * ldb;

    // cp.async geometry: 2048 16B-chunks per stage (A:1024, B:1024), 8 per thread
    const int ld_row = tid >> 3;          // 0..31 (stepped by +32)
    const int ld_s   = tid & 7;           // 16B slot in 128B row
    const uint32_t ld_sw = (uint32_t)((ld_s ^ (ld_row & 7)) << 4);

    auto load_stage = [&](int stg, int kt) {
        const char* ap = (const char*)(Ab + (size_t)kt * TBK) + ld_s * 16;
        const char* bp = (const char*)(Bb + (size_t)kt * TBK) + ld_s * 16;
        uint32_t smA = sb + stg * STAGE_BYTES;
        uint32_t smB = smA + A_BYTES;
        #pragma unroll
        for (int p = 0; p < 4; p++) {
            int r = ld_row + p * 32;
            cp16(smA + r * 128 + ld_sw, ap + (size_t)r * lda * 2);
        }
        #pragma unroll
        for (int p = 0; p < 4; p++) {
            int r = ld_row + p * 32;
            cp16(smB + r * 128 + ld_sw, bp + (size_t)r * ldb * 2);
        }
        asm volatile("cp.async.commit_group;" ::: "memory");
    };

    float acc[2][8][4];
    #pragma unroll
    for (int i = 0; i < 2; i++)
        #pragma unroll
        for (int j = 0; j < 8; j++)
            #pragma unroll
            for (int k = 0; k < 4; k++) acc[i][j][k] = 0.f;

    const int KT = Kd / TBK;
    load_stage(0, 0);
    if (KT > 1) load_stage(1, 1);
    else        asm volatile("cp.async.commit_group;" ::: "memory");

    // per-lane ldmatrix base addresses (row & 7 == lane & 7 for all tiles)
    const int l15 = lane & 15, l7 = lane & 7, lhi = lane >> 4;

    for (int kt = 0; kt < KT; kt++) {
        asm volatile("cp.async.wait_group 1;" ::: "memory");
        __syncthreads();
        if (kt + 2 < KT) load_stage((kt + 2) % NSTAGE, kt + 2);

        const uint32_t smA = sb + (kt % NSTAGE) * STAGE_BYTES;
        const uint32_t smB = smA + A_BYTES;
        const uint32_t arow = smA + (wm + l15) * 128;
        const uint32_t brow = smB + (wn + l15) * 128;

        #pragma unroll
        for (int ks = 0; ks < 4; ks++) {
            const uint32_t sw = (uint32_t)(((ks * 2 + lhi) ^ l7) << 4);
            uint32_t a[2][4], b[4][4];
            #pragma unroll
            for (int mt = 0; mt < 2; mt++) ldsm_x4(a[mt], arow + mt * 16 * 128 + sw);
            #pragma unroll
            for (int nt2 = 0; nt2 < 4; nt2++) ldsm_x4(b[nt2], brow + nt2 * 16 * 128 + sw);
            #pragma unroll
            for (int mt = 0; mt < 2; mt++)
                #pragma unroll
                for (int nt = 0; nt < 8; nt++) {
                    uint32_t bf[2] = { b[nt >> 1][nt & 1], b[nt >> 1][(nt & 1) + 2] };
                    mma16816(acc[mt][nt], a[mt], bf);
                }
        }
        __syncthreads();
    }

    // ---------------- epilogue ----------------
    const int er = lane >> 2, ec = (lane & 3) * 2;
    #pragma unroll
    for (int mt = 0; mt < 2; mt++) {
        const int row0 = cta_m + wm + mt * 16 + er;
        #pragma unroll
        for (int nt = 0; nt < 8; nt++) {
            const int col = cta_n + wn + nt * 8 + ec;
            if (OUT_HALF) {
                __half* C = (__half*)Cv + sC * blockIdx.z;
                *(__half2*)&C[(size_t)row0 * ldc + col] =
                    __floats2half2_rn(acc[mt][nt][0] * alpha, acc[mt][nt][1] * alpha);
                *(__half2*)&C[(size_t)(row0 + 8) * ldc + col] =
                    __floats2half2_rn(acc[mt][nt][2] * alpha, acc[mt][nt][3] * alpha);
            } else {
                float* C = (float*)Cv + sC * blockIdx.z;
                *(float2*)&C[(size_t)row0 * ldc + col] =
                    make_float2(acc[mt][nt][0] * alpha, acc[mt][nt][1] * alpha);
                *(float2*)&C[(size_t)(row0 + 8) * ldc + col] =
                    make_float2(acc[mt][nt][2] * alpha, acc[mt][nt][3] * alpha);
            }
        }
    }
}

// ---------------- fp32 -> fp16 convert ----------------
__global__ void f32_to_f16(const float* __restrict__ in, __half* __restrict__ out, int n4)
{
    int i = blockIdx.x * blockDim.x + threadIdx.x;
    if (i < n4) {
        float4 v = ((const float4*)in)[i];
        __half2 h0 = __floats2half2_rn(v.x, v.y);
        __half2 h1 = __floats2half2_rn(v.z, v.w);
        ((uint2*)out)[i] = make_uint2(*(uint32_t*)&h0, *(uint32_t*)&h1);
    }
}

// ---------------- softmax: fp32 logits in, fp16 P out ----------------
__global__ void softmax_rows(const float* __restrict__ logits, __half* __restrict__ P)
{
    __shared__ float red[8];
    __shared__ float bcast;
    const size_t row = blockIdx.x;
    const float* p = logits + row * (size_t)S_LEN;
    __half* q = P + row * (size_t)S_LEN;
    const int tid = threadIdx.x;
    const int lane = tid & 31, wid = tid >> 5;

    float4 v[4];
    float m = -3.4e38f;
    #pragma unroll
    for (int i = 0; i < 4; i++) {
        v[i] = *(const float4*)(p + tid * 4 + i * 1024);
        m = fmaxf(m, fmaxf(fmaxf(v[i].x, v[i].y), fmaxf(v[i].z, v[i].w)));
    }
    #pragma unroll
    for (int o = 16; o; o >>= 1) m = fmaxf(m, __shfl_xor_sync(0xffffffffu, m, o));
    if (lane == 0) red[wid] = m;
    __syncthreads();
    if (tid == 0) {
        float mm = red[0];
        #pragma unroll
        for (int i = 1; i < 8; i++) mm = fmaxf(mm, red[i]);
        bcast = mm;
    }
    __syncthreads();
    m = bcast;

    float s = 0.f;
    #pragma unroll
    for (int i = 0; i < 4; i++) {
        v[i].x = __expf(v[i].x - m);
        v[i].y = __expf(v[i].y - m);
        v[i].z = __expf(v[i].z - m);
        v[i].w = __expf(v[i].w - m);
        s += v[i].x + v[i].y + v[i].z + v[i].w;
    }
    #pragma unroll
    for (int o = 16; o; o >>= 1) s += __shfl_xor_sync(0xffffffffu, s, o);
    if (lane == 0) red[wid] = s;
    __syncthreads();
    if (tid == 0) {
        float ss = 0.f;
        #pragma unroll
        for (int i = 0; i < 8; i++) ss += red[i];
        bcast = 1.0f / ss;
    }
    __syncthreads();
    const float inv = bcast;

    #pragma unroll
    for (int i = 0; i < 4; i++) {
        *(__half2*)(q + tid * 4 + i * 1024)     = __floats2half2_rn(v[i].x * inv, v[i].y * inv);
        *(__half2*)(q + tid * 4 + i * 1024 + 2) = __floats2half2_rn(v[i].z * inv, v[i].w * inv);
    }
}

// ---------------- V transpose (fp16): vt[b][d][s] = qkvh[b][s][2D + d] ----------------
__global__ void transpose_v(const __half* __restrict__ qkvh, __half* __restrict__ vt)
{
    __shared__ __half t[32][33];
    const int b = blockIdx.z;
    const __half* src = qkvh + (size_t)b * S_LEN * 3 * D_MODEL + 2 * D_MODEL;
    __half* dst = vt + (size_t)b * D_MODEL * S_LEN;
    const int s0 = blockIdx.x * 32, d0 = blockIdx.y * 32;
    #pragma unroll
    for (int i = 0; i < 32; i += 8)
        t[threadIdx.y + i][threadIdx.x] =
            src[(size_t)(s0 + threadIdx.y + i) * (3 * D_MODEL) + d0 + threadIdx.x];
    __syncthreads();
    #pragma unroll
    for (int i = 0; i < 32; i += 8)
        dst[(size_t)(d0 + threadIdx.y + i) * S_LEN + s0 + threadIdx.x] =
            t[threadIdx.x][threadIdx.y + i];
}

// ---------------- launch ----------------
extern "C" void kernel_launch(void* const* d_in, const int* in_sizes, int n_in,
                              void* d_out, int out_size)
{
    const float* x    = (const float*)d_in[0];
    const float* wqkv = (const float*)d_in[1];
    const float* wo   = (const float*)d_in[2];
    float* out        = (float*)d_out;

    float  *logits;
    __half *ph, *qkvh, *xh, *wqkvh, *woh, *vth, *attnh;
    cudaGetSymbolAddress((void**)&logits, g_logits);
    cudaGetSymbolAddress((void**)&ph,     g_ph);
    cudaGetSymbolAddress((void**)&qkvh,   g_qkvh);
    cudaGetSymbolAddress((void**)&xh,     g_xh);
    cudaGetSymbolAddress((void**)&wqkvh,  g_wqkvh);
    cudaGetSymbolAddress((void**)&woh,    g_woh);
    cudaGetSymbolAddress((void**)&vth,    g_vth);
    cudaGetSymbolAddress((void**)&attnh,  g_attnh);

    cudaFuncSetAttribute(gemm_f16<true>,  cudaFuncAttributeMaxDynamicSharedMemorySize, SMEM_TOTAL);
    cudaFuncSetAttribute(gemm_f16<false>, cudaFuncAttributeMaxDynamicSharedMemorySize, SMEM_TOTAL);

    const int BS = BATCH * S_LEN;                      // 16384
    const size_t qkv_bs = (size_t)S_LEN * 3 * D_MODEL;
    const size_t log_bs = (size_t)S_LEN * S_LEN;
    const size_t att_bs = (size_t)S_LEN * D_MODEL;
    const size_t vt_bs  = (size_t)D_MODEL * S_LEN;

    // 0) fp32 -> fp16 input conversion
    {
        int nx = BS * D_MODEL / 4;
        f32_to_f16<<<(nx + 255) / 256, 256>>>(x, xh, nx);
        int nw = 3 * D_MODEL * D_MODEL / 4;
        f32_to_f16<<<(nw + 255) / 256, 256>>>(wqkv, wqkvh, nw);
        int no = D_MODEL * D_MODEL / 4;
        f32_to_f16<<<(no + 255) / 256, 256>>>(wo, woh, no);
    }

    // 1) qkvh = xh @ W_qkv^T   [16384 x 3072, K=1024] -> fp16
    gemm_f16<true><<<dim3(3 * D_MODEL / TN, BS / TM, 1), 256, SMEM_TOTAL>>>(
        xh, wqkvh, qkvh, D_MODEL, D_MODEL, D_MODEL, 3 * D_MODEL, 0, 0, 0, 1.0f);

    // 2) logits = (Q @ K^T)/32 [4096 x 4096, K=1024] x4 -> fp32
    gemm_f16<false><<<dim3(S_LEN / TN, S_LEN / TM, BATCH), 256, SMEM_TOTAL>>>(
        qkvh, qkvh + D_MODEL, logits, D_MODEL, 3 * D_MODEL, 3 * D_MODEL, S_LEN,
        qkv_bs, qkv_bs, log_bs, 0.03125f);

    // 3) softmax rows -> fp16 P
    softmax_rows<<<BS, 256>>>(logits, ph);

    // 4) V transpose -> fp16 vt
    transpose_v<<<dim3(S_LEN / 32, D_MODEL / 32, BATCH), dim3(32, 8)>>>(qkvh, vth);

    // 5) attnh = P @ Vt^T  [4096 x 1024, K=4096] x4 -> fp16
    gemm_f16<true><<<dim3(D_MODEL / TN, S_LEN / TM, BATCH), 256, SMEM_TOTAL>>>(
        ph, vth, attnh, S_LEN, S_LEN, S_LEN, D_MODEL,
        log_bs, vt_bs, att_bs, 1.0f);

    // 6) out = attnh @ W_o^T   [16384 x 1024, K=1024] -> fp32
    gemm_f16<false><<<dim3(D_MODEL / TN, BS / TM, 1), 256, SMEM_TOTAL>>>(
        attnh, woh, out, D_MODEL, D_MODEL, D_MODEL, D_MODEL, 0, 0, 0, 1.0f);
}

// round 4
// speedup vs baseline: 3.4001x; 1.0237x over previous
#include <cuda_runtime.h>
#include <cuda_fp16.h>
#include <cstdint>

#define BATCH 4
#define S_LEN 4096
#define D_MODEL 1024

// ---------------- scratch (module-load device globals) ----------------
__device__ float  g_logits[(size_t)BATCH * S_LEN * S_LEN];              // fp32 [B,S,S]
__device__ __half g_ph[(size_t)BATCH * S_LEN * S_LEN];                  // fp16 softmax(P)
__device__ __half g_qkvh[(size_t)BATCH * S_LEN * 3 * D_MODEL];          // fp16 [B,S,3D]
__device__ __half g_xh[(size_t)BATCH * S_LEN * D_MODEL];                // fp16 x
__device__ __half g_wqkvh[(size_t)3 * D_MODEL * D_MODEL];               // fp16 W_qkv
__device__ __half g_woh[(size_t)D_MODEL * D_MODEL];                     // fp16 W_o
__device__ __half g_vth[(size_t)BATCH * D_MODEL * S_LEN];               // fp16 V^T [B,D,S]
__device__ __half g_attnh[(size_t)BATCH * S_LEN * D_MODEL];             // fp16 attn

// ---------------- helpers ----------------
__device__ __forceinline__ uint32_t smem_u32(const void* p) {
    uint32_t a;
    asm("{ .reg .u64 t; cvta.to.shared.u64 t, %1; cvt.u32.u64 %0, t; }" : "=r"(a) : "l"(p));
    return a;
}
__device__ __forceinline__ void cp16(uint32_t dst, const void* src) {
    asm volatile("cp.async.cg.shared.global [%0], [%1], 16;" :: "r"(dst), "l"(src));
}
__device__ __forceinline__ void ldsm_x4(uint32_t* r, uint32_t addr) {
    asm volatile("ldmatrix.sync.aligned.m8n8.x4.shared.b16 {%0,%1,%2,%3}, [%4];"
                 : "=r"(r[0]), "=r"(r[1]), "=r"(r[2]), "=r"(r[3]) : "r"(addr));
}
__device__ __forceinline__ void mma16816(float* c, const uint32_t* a, const uint32_t* b) {
    asm volatile(
        "mma.sync.aligned.m16n8k16.row.col.f32.f16.f16.f32 "
        "{%0,%1,%2,%3}, {%4,%5,%6,%7}, {%8,%9}, {%0,%1,%2,%3};"
        : "+f"(c[0]), "+f"(c[1]), "+f"(c[2]), "+f"(c[3])
        : "r"(a[0]), "r"(a[1]), "r"(a[2]), "r"(a[3]), "r"(b[0]), "r"(b[1]));
}

// ---------------- fp16 NT GEMM: C[M,N] = alpha * A[M,K] @ B[N,K]^T ----------------
// CTA tile 128x128, BK=64 (128B rows), 3-stage cp.async pipeline, ldmatrix feeds,
// explicit ks-level fragment double-buffering, single barrier per k-tile.
#define TM 128
#define TN 128
#define TBK 64
#define A_BYTES (TM * TBK * 2)            // 16384
#define STAGE_BYTES ((TM + TN) * TBK * 2) // 32768
#define NSTAGE 3
#define SMEM_TOTAL (NSTAGE * STAGE_BYTES) // 98304

template<bool OUT_HALF>
__global__ void __launch_bounds__(256, 2)
gemm_f16(const __half* __restrict__ A, const __half* __restrict__ B, void* __restrict__ Cv,
         int Kd, int lda, int ldb, int ldc,
         size_t sA, size_t sB, size_t sC, float alpha)
{
    extern __shared__ char smem[];
    const uint32_t sb = smem_u32(smem);
    const int tid  = threadIdx.x;
    const int warp = tid >> 5, lane = tid & 31;
    const int wm = (warp & 3) * 32;       // 4 warps along M
    const int wn = (warp >> 2) * 64;      // 2 warps along N

    const int cta_m = blockIdx.y * TM;
    const int cta_n = blockIdx.x * TN;
    const __half* Ab = A + sA * blockIdx.z + (size_t)cta_m * lda;
    const __half* Bb = B + sB * blockIdx.z + (size_t)cta_n * ldb;

    // cp.async geometry: per stage A:1024 + B:1024 16B-chunks, 8 per thread
    const int ld_row = tid >> 3;          // 0..31 (stepped by +32)
    const int ld_s   = tid & 7;
    const uint32_t ld_sw = (uint32_t)((ld_s ^ (ld_row & 7)) << 4);

    // hoisted global src pointers (advance by kt*TBK elements inside)
    const char* a_src[4];
    const char* b_src[4];
    uint32_t a_dst[4], b_dst[4];
    #pragma unroll
    for (int p = 0; p < 4; p++) {
        int r = ld_row + p * 32;
        a_src[p] = (const char*)(Ab + (size_t)r * lda) + ld_s * 16;
        b_src[p] = (const char*)(Bb + (size_t)r * ldb) + ld_s * 16;
        a_dst[p] = (uint32_t)(r * 128) + ld_sw;
        b_dst[p] = (uint32_t)(r * 128) + ld_sw + A_BYTES;
    }

    auto load_stage = [&](uint32_t stoff, int kt) {
        const size_t koff = (size_t)kt * TBK * 2;
        const uint32_t base = sb + stoff;
        #pragma unroll
        for (int p = 0; p < 4; p++) cp16(base + a_dst[p], a_src[p] + koff);
        #pragma unroll
        for (int p = 0; p < 4; p++) cp16(base + b_dst[p], b_src[p] + koff);
        asm volatile("cp.async.commit_group;" ::: "memory");
    };

    float acc[2][8][4];
    #pragma unroll
    for (int i = 0; i < 2; i++)
        #pragma unroll
        for (int j = 0; j < 8; j++)
            #pragma unroll
            for (int k = 0; k < 4; k++) acc[i][j][k] = 0.f;

    const int KT = Kd / TBK;
    load_stage(0, 0);
    if (KT > 1) load_stage(STAGE_BYTES, 1);
    else        asm volatile("cp.async.commit_group;" ::: "memory");

    // per-lane ldmatrix geometry
    const int l15 = lane & 15, l7 = lane & 7, lhi = lane >> 4;
    uint32_t swk[4];
    #pragma unroll
    for (int ks = 0; ks < 4; ks++) swk[ks] = (uint32_t)(((ks * 2 + lhi) ^ l7) << 4);
    const uint32_t arow_off = (uint32_t)((wm + l15) * 128);
    const uint32_t brow_off = (uint32_t)((wn + l15) * 128) + A_BYTES;

    uint32_t cur_off = 0;                          // stage offset of tile kt
    uint32_t pre_off = 2 * STAGE_BYTES;            // stage offset of tile kt+2

    for (int kt = 0; kt < KT; kt++) {
        asm volatile("cp.async.wait_group 1;" ::: "memory");
        __syncthreads();
        if (kt + 2 < KT) load_stage(pre_off, kt + 2);

        const uint32_t arow = sb + cur_off + arow_off;
        const uint32_t brow = sb + cur_off + brow_off;

        uint32_t af[2][2][4], bf[2][4][4];
        // preload ks=0 fragments
        #pragma unroll
        for (int mt = 0; mt < 2; mt++) ldsm_x4(af[0][mt], arow + mt * 2048 + swk[0]);
        #pragma unroll
        for (int nt2 = 0; nt2 < 4; nt2++) ldsm_x4(bf[0][nt2], brow + nt2 * 2048 + swk[0]);

        #pragma unroll
        for (int ks = 0; ks < 4; ks++) {
            const int c = ks & 1, n = c ^ 1;
            if (ks < 3) {
                #pragma unroll
                for (int mt = 0; mt < 2; mt++) ldsm_x4(af[n][mt], arow + mt * 2048 + swk[ks + 1]);
                #pragma unroll
                for (int nt2 = 0; nt2 < 4; nt2++) ldsm_x4(bf[n][nt2], brow + nt2 * 2048 + swk[ks + 1]);
            }
            #pragma unroll
            for (int mt = 0; mt < 2; mt++)
                #pragma unroll
                for (int nt = 0; nt < 8; nt++) {
                    uint32_t bb[2] = { bf[c][nt >> 1][nt & 1], bf[c][nt >> 1][(nt & 1) + 2] };
                    mma16816(acc[mt][nt], af[c][mt], bb);
                }
        }

        // rotate stage offsets
        uint32_t t = cur_off;
        cur_off = (cur_off == 2 * STAGE_BYTES) ? 0u : cur_off + STAGE_BYTES;
        pre_off = t;
    }

    // ---------------- epilogue ----------------
    const int er = lane >> 2, ec = (lane & 3) * 2;
    #pragma unroll
    for (int mt = 0; mt < 2; mt++) {
        const int row0 = cta_m + wm + mt * 16 + er;
        #pragma unroll
        for (int nt = 0; nt < 8; nt++) {
            const int col = cta_n + wn + nt * 8 + ec;
            if (OUT_HALF) {
                __half* C = (__half*)Cv + sC * blockIdx.z;
                *(__half2*)&C[(size_t)row0 * ldc + col] =
                    __floats2half2_rn(acc[mt][nt][0] * alpha, acc[mt][nt][1] * alpha);
                *(__half2*)&C[(size_t)(row0 + 8) * ldc + col] =
                    __floats2half2_rn(acc[mt][nt][2] * alpha, acc[mt][nt][3] * alpha);
            } else {
                float* C = (float*)Cv + sC * blockIdx.z;
                *(float2*)&C[(size_t)row0 * ldc + col] =
                    make_float2(acc[mt][nt][0] * alpha, acc[mt][nt][1] * alpha);
                *(float2*)&C[(size_t)(row0 + 8) * ldc + col] =
                    make_float2(acc[mt][nt][2] * alpha, acc[mt][nt][3] * alpha);
            }
        }
    }
}

// ---------------- fp32 -> fp16 convert ----------------
__global__ void f32_to_f16(const float* __restrict__ in, __half* __restrict__ out, int n4)
{
    int i = blockIdx.x * blockDim.x + threadIdx.x;
    if (i < n4) {
        float4 v = ((const float4*)in)[i];
        __half2 h0 = __floats2half2_rn(v.x, v.y);
        __half2 h1 = __floats2half2_rn(v.z, v.w);
        ((uint2*)out)[i] = make_uint2(*(uint32_t*)&h0, *(uint32_t*)&h1);
    }
}

// ---------------- softmax: fp32 logits in, fp16 P out ----------------
__global__ void softmax_rows(const float* __restrict__ logits, __half* __restrict__ P)
{
    __shared__ float red[8];
    __shared__ float bcast;
    const size_t row = blockIdx.x;
    const float* p = logits + row * (size_t)S_LEN;
    __half* q = P + row * (size_t)S_LEN;
    const int tid = threadIdx.x;
    const int lane = tid & 31, wid = tid >> 5;

    float4 v[4];
    float m = -3.4e38f;
    #pragma unroll
    for (int i = 0; i < 4; i++) {
        v[i] = *(const float4*)(p + tid * 4 + i * 1024);
        m = fmaxf(m, fmaxf(fmaxf(v[i].x, v[i].y), fmaxf(v[i].z, v[i].w)));
    }
    #pragma unroll
    for (int o = 16; o; o >>= 1) m = fmaxf(m, __shfl_xor_sync(0xffffffffu, m, o));
    if (lane == 0) red[wid] = m;
    __syncthreads();
    if (tid == 0) {
        float mm = red[0];
        #pragma unroll
        for (int i = 1; i < 8; i++) mm = fmaxf(mm, red[i]);
        bcast = mm;
    }
    __syncthreads();
    m = bcast;

    float s = 0.f;
    #pragma unroll
    for (int i = 0; i < 4; i++) {
        v[i].x = __expf(v[i].x - m);
        v[i].y = __expf(v[i].y - m);
        v[i].z = __expf(v[i].z - m);
        v[i].w = __expf(v[i].w - m);
        s += v[i].x + v[i].y + v[i].z + v[i].w;
    }
    #pragma unroll
    for (int o = 16; o; o >>= 1) s += __shfl_xor_sync(0xffffffffu, s, o);
    if (lane == 0) red[wid] = s;
    __syncthreads();
    if (tid == 0) {
        float ss = 0.f;
        #pragma unroll
        for (int i = 0; i < 8; i++) ss += red[i];
        bcast = 1.0f / ss;
    }
    __syncthreads();
    const float inv = bcast;

    #pragma unroll
    for (int i = 0; i < 4; i++) {
        *(__half2*)(q + tid * 4 + i * 1024)     = __floats2half2_rn(v[i].x * inv, v[i].y * inv);
        *(__half2*)(q + tid * 4 + i * 1024 + 2) = __floats2half2_rn(v[i].z * inv, v[i].w * inv);
    }
}

// ---------------- V transpose (fp16): vt[b][d][s] = qkvh[b][s][2D + d] ----------------
__global__ void transpose_v(const __half* __restrict__ qkvh, __half* __restrict__ vt)
{
    __shared__ __half t[32][33];
    const int b = blockIdx.z;
    const __half* src = qkvh + (size_t)b * S_LEN * 3 * D_MODEL + 2 * D_MODEL;
    __half* dst = vt + (size_t)b * D_MODEL * S_LEN;
    const int s0 = blockIdx.x * 32, d0 = blockIdx.y * 32;
    #pragma unroll
    for (int i = 0; i < 32; i += 8)
        t[threadIdx.y + i][threadIdx.x] =
            src[(size_t)(s0 + threadIdx.y + i) * (3 * D_MODEL) + d0 + threadIdx.x];
    __syncthreads();
    #pragma unroll
    for (int i = 0; i < 32; i += 8)
        dst[(size_t)(d0 + threadIdx.y + i) * S_LEN + s0 + threadIdx.x] =
            t[threadIdx.x][threadIdx.y + i];
}

// ---------------- launch ----------------
extern "C" void kernel_launch(void* const* d_in, const int* in_sizes, int n_in,
                              void* d_out, int out_size)
{
    const float* x    = (const float*)d_in[0];
    const float* wqkv = (const float*)d_in[1];
    const float* wo   = (const float*)d_in[2];
    float* out        = (float*)d_out;

    float  *logits;
    __half *ph, *qkvh, *xh, *wqkvh, *woh, *vth, *attnh;
    cudaGetSymbolAddress((void**)&logits, g_logits);
    cudaGetSymbolAddress((void**)&ph,     g_ph);
    cudaGetSymbolAddress((void**)&qkvh,   g_qkvh);
    cudaGetSymbolAddress((void**)&xh,     g_xh);
    cudaGetSymbolAddress((void**)&wqkvh,  g_wqkvh);
    cudaGetSymbolAddress((void**)&woh,    g_woh);
    cudaGetSymbolAddress((void**)&vth,    g_vth);
    cudaGetSymbolAddress((void**)&attnh,  g_attnh);

    cudaFuncSetAttribute(gemm_f16<true>,  cudaFuncAttributeMaxDynamicSharedMemorySize, SMEM_TOTAL);
    cudaFuncSetAttribute(gemm_f16<false>, cudaFuncAttributeMaxDynamicSharedMemorySize, SMEM_TOTAL);

    const int BS = BATCH * S_LEN;                      // 16384
    const size_t qkv_bs = (size_t)S_LEN * 3 * D_MODEL;
    const size_t log_bs = (size_t)S_LEN * S_LEN;
    const size_t att_bs = (size_t)S_LEN * D_MODEL;
    const size_t vt_bs  = (size_t)D_MODEL * S_LEN;

    // 0) fp32 -> fp16 input conversion
    {
        int nx = BS * D_MODEL / 4;
        f32_to_f16<<<(nx + 255) / 256, 256>>>(x, xh, nx);
        int nw = 3 * D_MODEL * D_MODEL / 4;
        f32_to_f16<<<(nw + 255) / 256, 256>>>(wqkv, wqkvh, nw);
        int no = D_MODEL * D_MODEL / 4;
        f32_to_f16<<<(no + 255) / 256, 256>>>(wo, woh, no);
    }

    // 1) qkvh = xh @ W_qkv^T   [16384 x 3072, K=1024] -> fp16
    gemm_f16<true><<<dim3(3 * D_MODEL / TN, BS / TM, 1), 256, SMEM_TOTAL>>>(
        xh, wqkvh, qkvh, D_MODEL, D_MODEL, D_MODEL, 3 * D_MODEL, 0, 0, 0, 1.0f);

    // 2) logits = (Q @ K^T)/32 [4096 x 4096, K=1024] x4 -> fp32
    gemm_f16<false><<<dim3(S_LEN / TN, S_LEN / TM, BATCH), 256, SMEM_TOTAL>>>(
        qkvh, qkvh + D_MODEL, logits, D_MODEL, 3 * D_MODEL, 3 * D_MODEL, S_LEN,
        qkv_bs, qkv_bs, log_bs, 0.03125f);

    // 3) softmax rows -> fp16 P
    softmax_rows<<<BS, 256>>>(logits, ph);

    // 4) V transpose -> fp16 vt
    transpose_v<<<dim3(S_LEN / 32, D_MODEL / 32, BATCH), dim3(32, 8)>>>(qkvh, vth);

    // 5) attnh = P @ Vt^T  [4096 x 1024, K=4096] x4 -> fp16
    gemm_f16<true><<<dim3(D_MODEL / TN, S_LEN / TM, BATCH), 256, SMEM_TOTAL>>>(
        ph, vth, attnh, S_LEN, S_LEN, S_LEN, D_MODEL,
        log_bs, vt_bs, att_bs, 1.0f);

    // 6) out = attnh @ W_o^T   [16384 x 1024, K=1024] -> fp32
    gemm_f16<false><<<dim3(D_MODEL / TN, BS / TM, 1), 256, SMEM_TOTAL>>>(
        attnh, woh, out, D_MODEL, D_MODEL, D_MODEL, D_MODEL, 0, 0, 0, 1.0f);
}